// round 1
// baseline (speedup 1.0000x reference)
#include <cuda_runtime.h>

// Problem constants (fixed by the dataset: direction=0 -> sequence axis D, forward)
#define HH 256
#define WW 256
#define TT 64
#define BB 4
#define HWsz (HH * WW)        // 65536
#define BSTR (TT * HWsz)      // per-batch stride in x / out

// Cell state scratch (1 MB). Device global: allocation-free per harness rules.
__device__ float g_c[BB * HWsz];

__device__ __forceinline__ float sigf(float x) {
    // 1 / (1 + e^-x), ~1e-6 rel err
    return __fdividef(1.0f, 1.0f + __expf(-x));
}
__device__ __forceinline__ float tanhx(float x) {
    // 1 - 2/(e^{2x}+1); saturates correctly at +-inf via rcp(inf)=0
    return 1.0f - __fdividef(2.0f, __expf(2.0f * x) + 1.0f);
}

// One conv channel over an 8-row x 1-col strip, 25 weights in registers.
// tile rows: smem row r == global row (by + r - 2). Output local row lr uses smem rows lr..lr+4.
__device__ __forceinline__ void conv_pass8(const float (*__restrict__ tile)[36],
                                           int lr0, int tx,
                                           const float* __restrict__ wsm,
                                           float acc[8]) {
    float w[25];
#pragma unroll
    for (int i = 0; i < 25; i++) w[i] = wsm[i];
#pragma unroll
    for (int r = 0; r < 8; r++) acc[r] = 0.0f;
#pragma unroll
    for (int rin = 0; rin < 12; rin++) {
        float d[5];
#pragma unroll
        for (int kw = 0; kw < 5; kw++) d[kw] = tile[lr0 + rin][tx + kw];
#pragma unroll
        for (int kh = 0; kh < 5; kh++) {
            const int orow = rin - kh;
            if (orow >= 0 && orow < 8) {
#pragma unroll
                for (int kw = 0; kw < 5; kw++)
                    acc[orow] = fmaf(d[kw], w[kh * 5 + kw], acc[orow]);
            }
        }
    }
}

// One LSTM time step. FIRST=true: h_prev == 0, c_prev == 0 (skip h conv entirely).
template <bool FIRST>
__global__ __launch_bounds__(128)
void clstm_step(const float* __restrict__ x_t,     // x + t*HWsz (batch offset added in-kernel)
                const float* __restrict__ h_prev,  // out + (t-1)*HWsz, unused when FIRST
                float* __restrict__ out_t,         // out + t*HWsz
                const float* __restrict__ Wx,
                const float* __restrict__ Wh,
                const float* __restrict__ bias) {
    __shared__ float xs[36][36];
    __shared__ float hs[36][36];
    __shared__ float ws[150];   // [conv(2)][chsel(3: ch 0,2,3)][kh][kw]
    __shared__ float bs[3];

    const int tx = threadIdx.x;          // 0..31
    const int ty = threadIdx.y;          // 0..3
    const int tid = ty * 32 + tx;
    const int bx = blockIdx.x * 32;
    const int by = blockIdx.y * 32;
    const int b  = blockIdx.z;

    const float* xb = x_t + b * BSTR;
    const float* hb = FIRST ? x_t : (h_prev + b * BSTR);  // dummy when FIRST

    // Pack weights for the used channels {0,2,3} in pass order.
    for (int i = tid; i < 153; i += 128) {
        if (i < 150) {
            const int conv = i / 75;
            const int rem  = i % 75;
            const int ci   = rem / 25;
            const int k    = rem % 25;
            const int ch   = (ci == 0) ? 0 : (ci + 1);  // 0,2,3
            ws[i] = (conv == 0) ? Wx[ch * 25 + k] : Wh[ch * 25 + k];
        } else {
            const int ci = i - 150;
            const int ch = (ci == 0) ? 0 : (ci + 1);
            bs[ci] = bias[ch];
        }
    }

    // Load 36x36 halo tiles (zero-padded).
    for (int i = tid; i < 36 * 36; i += 128) {
        const int r = i / 36, c = i % 36;
        const int gr = by + r - 2, gc = bx + c - 2;
        const bool inb = (gr >= 0) & (gr < HH) & (gc >= 0) & (gc < WW);
        xs[r][c] = inb ? xb[gr * WW + gc] : 0.0f;
        if (!FIRST) hs[r][c] = inb ? hb[gr * WW + gc] : 0.0f;
    }
    __syncthreads();

    const int lr0 = ty * 8;  // first output local row for this thread
    float z0[8], z2[8], z3[8];
    {
        float a[8];
        conv_pass8(xs, lr0, tx, ws + 0, a);
#pragma unroll
        for (int j = 0; j < 8; j++) z0[j] = fmaxf(a[j], 0.0f);
        conv_pass8(xs, lr0, tx, ws + 25, a);
#pragma unroll
        for (int j = 0; j < 8; j++) z2[j] = fmaxf(a[j], 0.0f);
        conv_pass8(xs, lr0, tx, ws + 50, a);
#pragma unroll
        for (int j = 0; j < 8; j++) z3[j] = fmaxf(a[j], 0.0f);
        if (!FIRST) {
            conv_pass8(hs, lr0, tx, ws + 75, a);
#pragma unroll
            for (int j = 0; j < 8; j++) z0[j] += fmaxf(a[j], 0.0f);
            conv_pass8(hs, lr0, tx, ws + 100, a);
#pragma unroll
            for (int j = 0; j < 8; j++) z2[j] += fmaxf(a[j], 0.0f);
            conv_pass8(hs, lr0, tx, ws + 125, a);
#pragma unroll
            for (int j = 0; j < 8; j++) z3[j] += fmaxf(a[j], 0.0f);
        }
    }

    const float b0 = bs[0], b2 = bs[1], b3 = bs[2];
    const int gr0 = by + lr0;
    const int gc  = bx + tx;
    const int cbase = b * HWsz + gr0 * WW + gc;
    float* ob = out_t + b * BSTR + gr0 * WW + gc;

#pragma unroll
    for (int j = 0; j < 8; j++) {
        const float cp = FIRST ? 0.0f : g_c[cbase + j * WW];
        const float ig = sigf(z0[j] + b0);
        const float cg = tanhx(z2[j] + b2);
        const float og = sigf(z3[j] + b3);
        const float cn = (cg + cp) * ig;
        g_c[cbase + j * WW] = cn;
        ob[j * WW] = og * tanhx(cn);
    }
}

extern "C" void kernel_launch(void* const* d_in, const int* in_sizes, int n_in,
                              void* d_out, int out_size) {
    const float* x    = (const float*)d_in[0];
    const float* Wx   = (const float*)d_in[1];
    const float* Wh   = (const float*)d_in[2];
    const float* bias = (const float*)d_in[3];
    // d_in[4] is `direction`; fixed to 0 for this problem (seq axis = D, forward).
    float* out = (float*)d_out;

    dim3 block(32, 4);
    dim3 grid(WW / 32, HH / 32, BB);  // (8, 8, 4) = 256 blocks

    clstm_step<true><<<grid, block>>>(x, nullptr, out, Wx, Wh, bias);
    for (int t = 1; t < TT; t++) {
        clstm_step<false><<<grid, block>>>(x + (size_t)t * HWsz,
                                           out + (size_t)(t - 1) * HWsz,
                                           out + (size_t)t * HWsz,
                                           Wx, Wh, bias);
    }
}

// round 15
// speedup vs baseline: 1.3889x; 1.3889x over previous
#include <cuda_runtime.h>

// Problem constants (fixed by dataset: direction=0 -> sequence axis D, forward)
#define HH 256
#define WW 256
#define TT 64
#define BB 4
#define HWsz (HH * WW)        // 65536
#define BSTR (TT * HWsz)      // per-batch stride in x / out

// Tile geometry: 32 cols x 16 rows per CTA, 128 threads (32x4), 4 rows/thread.
#define TROWS 16
#define SROWS 20              // TROWS + 4 halo
#define SCOLS 36
#define NBLK  512             // 8 * 16 * 4 tiles; co-resident (148 SMs * 4 = 592 slots)

// Cell state scratch (1 MB) + grid barrier counter. Device globals: allocation-free.
__device__ float g_c[BB * HWsz];
__device__ unsigned int g_count;

__device__ __forceinline__ float sigf(float x) {
    return __fdividef(1.0f, 1.0f + __expf(-x));
}
__device__ __forceinline__ float tanhx(float x) {
    return 1.0f - __fdividef(2.0f, __expf(2.0f * x) + 1.0f);
}

// One conv channel over a 4-row x 1-col strip, 25 weights in registers.
__device__ __forceinline__ void conv_pass4(const float (*__restrict__ tile)[SCOLS],
                                           int lr0, int tx,
                                           const float* __restrict__ wsm,
                                           float acc[4]) {
    float w[25];
#pragma unroll
    for (int i = 0; i < 25; i++) w[i] = wsm[i];
#pragma unroll
    for (int r = 0; r < 4; r++) acc[r] = 0.0f;
#pragma unroll
    for (int rin = 0; rin < 8; rin++) {
        float d[5];
#pragma unroll
        for (int kw = 0; kw < 5; kw++) d[kw] = tile[lr0 + rin][tx + kw];
#pragma unroll
        for (int kh = 0; kh < 5; kh++) {
            const int orow = rin - kh;
            if (orow >= 0 && orow < 4) {
#pragma unroll
                for (int kw = 0; kw < 5; kw++)
                    acc[orow] = fmaf(d[kw], w[kh * 5 + kw], acc[orow]);
            }
        }
    }
}

// Grid-wide barrier. Monotonic counter; all NBLK CTAs are co-resident by construction.
__device__ __forceinline__ void grid_barrier(unsigned int target, int tid) {
    __threadfence();          // publish this thread's global writes (to L2)
    __syncthreads();          // all threads of CTA have fenced
    if (tid == 0) {
        atomicAdd(&g_count, 1u);
        while (*(volatile unsigned int*)&g_count < target) __nanosleep(64);
    }
    __syncthreads();          // release whole CTA once thread 0 sees the barrier done
}

__global__ void reset_barrier() { g_count = 0u; }

__global__ __launch_bounds__(128, 4)
void clstm_persist(const float* __restrict__ x,
                   float* __restrict__ out,
                   const float* __restrict__ Wx,
                   const float* __restrict__ Wh,
                   const float* __restrict__ bias) {
    __shared__ float xs[SROWS][SCOLS];
    __shared__ float hs[SROWS][SCOLS];
    __shared__ float ws[150];   // [conv(2)][chsel(3: ch 0,2,3)][25]
    __shared__ float bs[3];

    const int tx  = threadIdx.x;          // 0..31
    const int ty  = threadIdx.y;          // 0..3
    const int tid = ty * 32 + tx;

    // Decode CTA -> tile (8 x-tiles, 16 y-tiles, 4 batches)
    const int bx = (blockIdx.x & 7) * 32;
    const int by = ((blockIdx.x >> 3) & 15) * TROWS;
    const int b  = blockIdx.x >> 7;

    // Pack weights once for the used channels {0,2,3} in pass order.
    // STRIDED LOOP: 153 items > 128 threads -> two trips. (The R5-R11 `if (tid<150)`
    // version silently dropped ws[128..149] and all of bs[] -> rel_err 0.37.)
    for (int i = tid; i < 153; i += 128) {
        if (i < 150) {
            const int conv = i / 75;
            const int rem  = i % 75;
            const int ci   = rem / 25;
            const int k    = rem % 25;
            const int ch   = (ci == 0) ? 0 : (ci + 1);  // 0,2,3
            ws[i] = (conv == 0) ? Wx[ch * 25 + k] : Wh[ch * 25 + k];
        } else {
            const int ci = i - 150;
            const int ch = (ci == 0) ? 0 : (ci + 1);
            bs[ci] = bias[ch];
        }
    }

    const int lr0 = ty * 4;
    const int gr0 = by + lr0;
    const int gc  = bx + tx;
    const int cbase = b * HWsz + gr0 * WW + gc;
    const float* xb = x + b * BSTR;
    float* outb     = out + b * BSTR;

    for (int t = 0; t < TT; t++) {
        const bool first = (t == 0);
        const float* xt = xb + (size_t)t * HWsz;
        const float* hp = outb + (size_t)(t - 1) * HWsz;   // only read when !first

        // Load halo tiles (zero-padded).
        // x is kernel-lifetime read-only -> __ldg. hp aliases `out`, written by
        // THIS kernel -> __ldcg (L2-coherent path, not the NC texture path).
#pragma unroll
        for (int i = tid; i < SROWS * SCOLS; i += 128) {
            const int r = i / SCOLS, c = i % SCOLS;
            const int gr = by + r - 2, gcl = bx + c - 2;
            const bool inb = (gr >= 0) & (gr < HH) & (gcl >= 0) & (gcl < WW);
            xs[r][c] = inb ? __ldg(xt + gr * WW + gcl) : 0.0f;
            hs[r][c] = (!first && inb) ? __ldcg(hp + gr * WW + gcl) : 0.0f;
        }
        __syncthreads();

        float z0[4], z2[4], z3[4];
        {
            float a[4];
            conv_pass4(xs, lr0, tx, ws + 0, a);
#pragma unroll
            for (int j = 0; j < 4; j++) z0[j] = fmaxf(a[j], 0.0f);
            conv_pass4(xs, lr0, tx, ws + 25, a);
#pragma unroll
            for (int j = 0; j < 4; j++) z2[j] = fmaxf(a[j], 0.0f);
            conv_pass4(xs, lr0, tx, ws + 50, a);
#pragma unroll
            for (int j = 0; j < 4; j++) z3[j] = fmaxf(a[j], 0.0f);
            if (!first) {
                conv_pass4(hs, lr0, tx, ws + 75, a);
#pragma unroll
                for (int j = 0; j < 4; j++) z0[j] += fmaxf(a[j], 0.0f);
                conv_pass4(hs, lr0, tx, ws + 100, a);
#pragma unroll
                for (int j = 0; j < 4; j++) z2[j] += fmaxf(a[j], 0.0f);
                conv_pass4(hs, lr0, tx, ws + 125, a);
#pragma unroll
                for (int j = 0; j < 4; j++) z3[j] += fmaxf(a[j], 0.0f);
            }
        }

        const float b0 = bs[0], b2 = bs[1], b3 = bs[2];
        float* ot = outb + (size_t)t * HWsz + gr0 * WW + gc;
#pragma unroll
        for (int j = 0; j < 4; j++) {
            const float cp = first ? 0.0f : g_c[cbase + j * WW];
            const float ig = sigf(z0[j] + b0);
            const float cg = tanhx(z2[j] + b2);
            const float og = sigf(z3[j] + b3);
            const float cn = (cg + cp) * ig;
            g_c[cbase + j * WW] = cn;
            ot[j * WW] = og * tanhx(cn);
        }

        // Publish out[t] / advance all CTAs together (also protects smem reuse).
        // Final step needs no barrier: nothing consumes out[TT-1] in-kernel.
        if (t < TT - 1) grid_barrier((unsigned)(t + 1) * NBLK, tid);
    }
}

extern "C" void kernel_launch(void* const* d_in, const int* in_sizes, int n_in,
                              void* d_out, int out_size) {
    const float* x    = (const float*)d_in[0];
    const float* Wx   = (const float*)d_in[1];
    const float* Wh   = (const float*)d_in[2];
    const float* bias = (const float*)d_in[3];
    float* out = (float*)d_out;

    reset_barrier<<<1, 1>>>();
    clstm_persist<<<NBLK, dim3(32, 4)>>>(x, out, Wx, Wh, bias);
}

// round 16
// speedup vs baseline: 1.4911x; 1.0736x over previous
#include <cuda_runtime.h>

// Problem constants (fixed by dataset: direction=0 -> sequence axis D, forward)
#define HH 256
#define WW 256
#define TT 64
#define BB 4
#define HWsz (HH * WW)        // 65536
#define BSTR (TT * HWsz)      // per-batch stride in x / out

// Tile geometry: 32 cols x 16 rows per CTA, 128 threads (32x4), 4 rows/thread.
#define TROWS 16
#define SROWS 20              // TROWS + 4 halo
#define SCOLS 36
#define NBLK  512             // 8 x-tiles * 16 y-tiles * 4 batches; co-resident (<=592 slots)

// Cell state scratch (1 MB) + per-tile progress flags (128B padded).
__device__ float g_c[BB * HWsz];
__device__ int   g_flag[NBLK * 32];   // slot [id*32]; 64 KB

__device__ __forceinline__ float sigf(float x) {
    return __fdividef(1.0f, 1.0f + __expf(-x));
}
__device__ __forceinline__ float tanhx(float x) {
    return 1.0f - __fdividef(2.0f, __expf(2.0f * x) + 1.0f);
}

// One conv channel over a 4-row x 1-col strip, 25 weights in registers.
__device__ __forceinline__ void conv_pass4(const float (*__restrict__ tile)[SCOLS],
                                           int lr0, int tx,
                                           const float* __restrict__ wsm,
                                           float acc[4]) {
    float w[25];
#pragma unroll
    for (int i = 0; i < 25; i++) w[i] = wsm[i];
#pragma unroll
    for (int r = 0; r < 4; r++) acc[r] = 0.0f;
#pragma unroll
    for (int rin = 0; rin < 8; rin++) {
        float d[5];
#pragma unroll
        for (int kw = 0; kw < 5; kw++) d[kw] = tile[lr0 + rin][tx + kw];
#pragma unroll
        for (int kh = 0; kh < 5; kh++) {
            const int orow = rin - kh;
            if (orow >= 0 && orow < 4) {
#pragma unroll
                for (int kw = 0; kw < 5; kw++)
                    acc[orow] = fmaf(d[kw], w[kh * 5 + kw], acc[orow]);
            }
        }
    }
}

__global__ void reset_flags() {
    const int i = blockIdx.x * blockDim.x + threadIdx.x;
    if (i < NBLK) g_flag[i * 32] = 0;
}

__global__ __launch_bounds__(128, 4)
void clstm_persist(const float* __restrict__ x,
                   float* __restrict__ out,
                   const float* __restrict__ Wx,
                   const float* __restrict__ Wh,
                   const float* __restrict__ bias) {
    __shared__ float xs[SROWS][SCOLS];
    __shared__ float hs[SROWS][SCOLS];
    __shared__ float ws[150];   // [conv(2)][chsel(3: ch 0,2,3)][25]
    __shared__ float bs[3];

    const int tx  = threadIdx.x;          // 0..31
    const int ty  = threadIdx.y;          // 0..3
    const int tid = ty * 32 + tx;

    // Decode CTA -> tile (8 x-tiles, 16 y-tiles, 4 batches)
    const int txl = blockIdx.x & 7;
    const int tyl = (blockIdx.x >> 3) & 15;
    const int b   = blockIdx.x >> 7;
    const int bx  = txl * 32;
    const int by  = tyl * TROWS;
    const int myid = blockIdx.x;

    // Neighbor tile ids (<=8; halo=2 only touches +-1 tiles in x and y, same batch).
    int nb[8]; int nnb = 0;
#pragma unroll
    for (int dy = -1; dy <= 1; dy++)
#pragma unroll
        for (int dx = -1; dx <= 1; dx++) {
            if (dx == 0 && dy == 0) continue;
            const int nx = txl + dx, ny = tyl + dy;
            if (nx >= 0 && nx < 8 && ny >= 0 && ny < 16)
                nb[nnb++] = (b << 7) + (ny << 3) + nx;
        }

    // Pack weights once for the used channels {0,2,3} in pass order.
    // Strided loop: 153 items > 128 threads -> two trips.
    for (int i = tid; i < 153; i += 128) {
        if (i < 150) {
            const int conv = i / 75;
            const int rem  = i % 75;
            const int ci   = rem / 25;
            const int k    = rem % 25;
            const int ch   = (ci == 0) ? 0 : (ci + 1);  // 0,2,3
            ws[i] = (conv == 0) ? Wx[ch * 25 + k] : Wh[ch * 25 + k];
        } else {
            const int ci = i - 150;
            const int ch = (ci == 0) ? 0 : (ci + 1);
            bs[ci] = bias[ch];
        }
    }

    const int lr0 = ty * 4;
    const int gr0 = by + lr0;
    const int gc  = bx + tx;
    const int cbase = b * HWsz + gr0 * WW + gc;
    const float* xb = x + b * BSTR;
    float* outb     = out + b * BSTR;

    for (int t = 0; t < TT; t++) {
        const bool first = (t == 0);
        const float* xt = xb + (size_t)t * HWsz;
        const float* hp = outb + (size_t)(t - 1) * HWsz;   // only read when !first

        // Wait for neighbors to publish out[t-1] (acquire side).
        if (!first) {
            if (tid < nnb) {
                volatile int* f = &g_flag[nb[tid] * 32];
                while (*f < t) __nanosleep(32);
                __threadfence();   // order subsequent data loads after flag observation
            }
            __syncthreads();       // whole CTA proceeds only after acquire completes
        }

        // Load halo tiles (zero-padded).
        // x is kernel-lifetime read-only -> __ldg. hp aliases `out`, written by
        // THIS kernel -> __ldcg (coherent L2 path, not the NC texture path).
#pragma unroll
        for (int i = tid; i < SROWS * SCOLS; i += 128) {
            const int r = i / SCOLS, c = i % SCOLS;
            const int gr = by + r - 2, gcl = bx + c - 2;
            const bool inb = (gr >= 0) & (gr < HH) & (gcl >= 0) & (gcl < WW);
            xs[r][c] = inb ? __ldg(xt + gr * WW + gcl) : 0.0f;
            hs[r][c] = (!first && inb) ? __ldcg(hp + gr * WW + gcl) : 0.0f;
        }
        __syncthreads();

        float z0[4], z2[4], z3[4];
        {
            float a[4];
            conv_pass4(xs, lr0, tx, ws + 0, a);
#pragma unroll
            for (int j = 0; j < 4; j++) z0[j] = fmaxf(a[j], 0.0f);
            conv_pass4(xs, lr0, tx, ws + 25, a);
#pragma unroll
            for (int j = 0; j < 4; j++) z2[j] = fmaxf(a[j], 0.0f);
            conv_pass4(xs, lr0, tx, ws + 50, a);
#pragma unroll
            for (int j = 0; j < 4; j++) z3[j] = fmaxf(a[j], 0.0f);
            if (!first) {
                conv_pass4(hs, lr0, tx, ws + 75, a);
#pragma unroll
                for (int j = 0; j < 4; j++) z0[j] += fmaxf(a[j], 0.0f);
                conv_pass4(hs, lr0, tx, ws + 100, a);
#pragma unroll
                for (int j = 0; j < 4; j++) z2[j] += fmaxf(a[j], 0.0f);
                conv_pass4(hs, lr0, tx, ws + 125, a);
#pragma unroll
                for (int j = 0; j < 4; j++) z3[j] += fmaxf(a[j], 0.0f);
            }
        }

        const float b0 = bs[0], b2 = bs[1], b3 = bs[2];
        float* ot = outb + (size_t)t * HWsz + gr0 * WW + gc;
#pragma unroll
        for (int j = 0; j < 4; j++) {
            const float cp = first ? 0.0f : g_c[cbase + j * WW];
            const float ig = sigf(z0[j] + b0);
            const float cg = tanhx(z2[j] + b2);
            const float og = sigf(z3[j] + b3);
            const float cn = (cg + cp) * ig;
            g_c[cbase + j * WW] = cn;
            ot[j * WW] = og * tanhx(cn);
        }

        // Publish out[t] (release side). Also separates this step's smem reads
        // from next step's smem writes. No flag needed after the last step.
        __syncthreads();
        if (t < TT - 1 && tid == 0) {
            __threadfence();                       // stores above visible device-wide
            *(volatile int*)&g_flag[myid * 32] = t + 1;
        }
    }
}

extern "C" void kernel_launch(void* const* d_in, const int* in_sizes, int n_in,
                              void* d_out, int out_size) {
    const float* x    = (const float*)d_in[0];
    const float* Wx   = (const float*)d_in[1];
    const float* Wh   = (const float*)d_in[2];
    const float* bias = (const float*)d_in[3];
    float* out = (float*)d_out;

    reset_flags<<<2, 256>>>();
    clstm_persist<<<NBLK, dim3(32, 4)>>>(x, out, Wx, Wh, bias);
}